// round 7
// baseline (speedup 1.0000x reference)
#include <cuda_runtime.h>
#include <cuda_bf16.h>
#include <cstdint>
#include <math.h>

// Problem constants
#define BATCH   2
#define TSEQ    2048
#define EMBED   1024
#define NHEAD   16
#define HDIM    64
#define MTOK    (BATCH * TSEQ)        // 4096
#define QKVCOLS (3 * EMBED)           // 3072

// Scratch (allocation-free rule: __device__ globals)
__device__ float         g_qkv[(size_t)MTOK * QKVCOLS];   // [4096, 3072]
__device__ float         g_att[(size_t)MTOK * EMBED];     // [4096, 1024]
__device__ __nv_bfloat16 g_xa_hi[(size_t)MTOK * EMBED];
__device__ __nv_bfloat16 g_xa_lo[(size_t)MTOK * EMBED];
__device__ __nv_bfloat16 g_wq_hi[(size_t)QKVCOLS * EMBED]; // w_qkv^T [3072][1024]
__device__ __nv_bfloat16 g_wq_lo[(size_t)QKVCOLS * EMBED];
__device__ __nv_bfloat16 g_wo_hi[(size_t)EMBED * EMBED];   // w_out^T [1024][1024]
__device__ __nv_bfloat16 g_wo_lo[(size_t)EMBED * EMBED];

// ---------------------------------------------------------------------------
// PTX helpers (all plain sm_80+ PTX — no arch-accelerated features)
// ---------------------------------------------------------------------------
__device__ __forceinline__ uint32_t smem_u32(const void* p) {
    uint32_t a;
    asm("{ .reg .u64 t; cvta.to.shared.u64 t, %1; cvt.u32.u64 %0, t; }"
        : "=r"(a) : "l"(p));
    return a;
}

#define CP_ASYNC16(dst, src) \
    asm volatile("cp.async.cg.shared.global [%0], [%1], 16;" :: "r"(dst), "l"(src))
#define CP_COMMIT()  asm volatile("cp.async.commit_group;" ::: "memory")
#define CP_WAIT0()   asm volatile("cp.async.wait_group 0;" ::: "memory")

#define LDSM_X4(r0, r1, r2, r3, a) \
    asm volatile("ldmatrix.sync.aligned.m8n8.x4.shared.b16 {%0,%1,%2,%3}, [%4];" \
                 : "=r"(r0), "=r"(r1), "=r"(r2), "=r"(r3) : "r"(a))

__device__ __forceinline__ void mma16816(float* d, const uint32_t* a,
                                         uint32_t b0, uint32_t b1) {
    asm volatile(
        "mma.sync.aligned.m16n8k16.row.col.f32.bf16.bf16.f32 "
        "{%0,%1,%2,%3}, {%4,%5,%6,%7}, {%8,%9}, {%0,%1,%2,%3};"
        : "+f"(d[0]), "+f"(d[1]), "+f"(d[2]), "+f"(d[3])
        : "r"(a[0]), "r"(a[1]), "r"(a[2]), "r"(a[3]), "r"(b0), "r"(b1));
}

__device__ __forceinline__ uint32_t swz(uint32_t o) {
    return o ^ ((o >> 3) & 0x70);
}

// ---------------------------------------------------------------------------
// Prep: split fp32 -> bf16 hi/lo (elementwise, vectorized)
// ---------------------------------------------------------------------------
__global__ __launch_bounds__(256) void split_kernel(
    const float* __restrict__ src, __nv_bfloat16* __restrict__ hi,
    __nv_bfloat16* __restrict__ lo, int n4)
{
    int i = blockIdx.x * blockDim.x + threadIdx.x;
    if (i >= n4) return;
    float4 v = ((const float4*)src)[i];
    __nv_bfloat16 h0 = __float2bfloat16(v.x), h1 = __float2bfloat16(v.y);
    __nv_bfloat16 h2 = __float2bfloat16(v.z), h3 = __float2bfloat16(v.w);
    __nv_bfloat16 l0 = __float2bfloat16(v.x - __bfloat162float(h0));
    __nv_bfloat16 l1 = __float2bfloat16(v.y - __bfloat162float(h1));
    __nv_bfloat16 l2 = __float2bfloat16(v.z - __bfloat162float(h2));
    __nv_bfloat16 l3 = __float2bfloat16(v.w - __bfloat162float(h3));
    __nv_bfloat162* hp = (__nv_bfloat162*)hi;
    __nv_bfloat162* lp = (__nv_bfloat162*)lo;
    hp[2*i]   = __nv_bfloat162(h0, h1);
    hp[2*i+1] = __nv_bfloat162(h2, h3);
    lp[2*i]   = __nv_bfloat162(l0, l1);
    lp[2*i+1] = __nv_bfloat162(l2, l3);
}

// ---------------------------------------------------------------------------
// Prep: transpose + split weights. W[K][N] fp32 -> WT_hi/lo [N][K] bf16
// ---------------------------------------------------------------------------
__global__ __launch_bounds__(256) void wsplit_kernel(
    const float* __restrict__ W, __nv_bfloat16* __restrict__ Thi,
    __nv_bfloat16* __restrict__ Tlo, int K, int N)
{
    __shared__ float t[32][33];
    int tx = threadIdx.x, ty = threadIdx.y;       // 32 x 8
    int k0 = blockIdx.y * 32, n0 = blockIdx.x * 32;
    #pragma unroll
    for (int i = 0; i < 4; i++)
        t[ty + i * 8][tx] = W[(size_t)(k0 + ty + i * 8) * N + n0 + tx];
    __syncthreads();
    #pragma unroll
    for (int i = 0; i < 4; i++) {
        float v = t[tx][ty + i * 8];
        __nv_bfloat16 h = __float2bfloat16(v);
        __nv_bfloat16 l = __float2bfloat16(v - __bfloat162float(h));
        size_t o = (size_t)(n0 + ty + i * 8) * K + k0 + tx;
        Thi[o] = h;
        Tlo[o] = l;
    }
}

// ---------------------------------------------------------------------------
// Warp-mma GEMM: C[M,N] = Ahi/lo[M,K=1024] @ (Bhi/lo[N,K])^T + bias
// 128x128 CTA tile, 8 warps (4m x 2n), 32x64 per warp.
// K chunk = 64 bf16 (128B rows), double-buffered via cp.async.
// Split product: Ah*Bh + Ah*Bl + Al*Bh, fp32 accum in registers.
// ---------------------------------------------------------------------------
#define GK      1024
#define NCHUNK  16            // 1024 / 64
#define TILE_B  16384         // 128 rows x 128 bytes
#define BUF_B   (4 * TILE_B)  // Ahi, Alo, Bhi, Blo
#define GEMM_SMEM (2 * BUF_B) // 131072

__device__ __forceinline__ void load_chunk_async(
    const __nv_bfloat16* __restrict__ Ahi, const __nv_bfloat16* __restrict__ Alo,
    const __nv_bfloat16* __restrict__ Bhi, const __nv_bfloat16* __restrict__ Blo,
    int bm, int bn, int kbyte, uint32_t buf, int tid)
{
    #pragma unroll
    for (int i = 0; i < 4; i++) {
        int idx = tid + i * 256;                  // 0..1023
        int r   = idx >> 3;                       // 0..127
        int cb  = (idx & 7) * 16;                 // byte within 128B row
        uint32_t so = swz((uint32_t)(r * 128 + cb));
        const char* gA = (const char*)(Ahi + (size_t)(bm + r) * GK) + kbyte + cb;
        const char* gAl= (const char*)(Alo + (size_t)(bm + r) * GK) + kbyte + cb;
        const char* gB = (const char*)(Bhi + (size_t)(bn + r) * GK) + kbyte + cb;
        const char* gBl= (const char*)(Blo + (size_t)(bn + r) * GK) + kbyte + cb;
        CP_ASYNC16(buf + so,              gA);
        CP_ASYNC16(buf + TILE_B + so,     gAl);
        CP_ASYNC16(buf + 2 * TILE_B + so, gB);
        CP_ASYNC16(buf + 3 * TILE_B + so, gBl);
    }
}

__global__ __launch_bounds__(256) void gemm_mma_kernel(
    const __nv_bfloat16* __restrict__ Ahi, const __nv_bfloat16* __restrict__ Alo,
    const __nv_bfloat16* __restrict__ Bhi, const __nv_bfloat16* __restrict__ Blo,
    const float* __restrict__ bias, float* __restrict__ C, int N)
{
    extern __shared__ char smem[];
    const uint32_t sb = smem_u32(smem);
    const int tid = threadIdx.x;
    const int wid = tid >> 5;
    const int lid = tid & 31;
    const int wm  = wid >> 1;       // 0..3 -> m offset wm*32
    const int wn  = wid & 1;        // 0..1 -> n offset wn*64

    const int bm = blockIdx.y * 128;
    const int bn = blockIdx.x * 128;

    float acc[2][8][4];
    #pragma unroll
    for (int a = 0; a < 2; a++)
        #pragma unroll
        for (int j = 0; j < 8; j++)
            #pragma unroll
            for (int k = 0; k < 4; k++) acc[a][j][k] = 0.0f;

    // Per-thread ldmatrix byte-offset bases (before swizzle, before ks term)
    // A: row = wm*32 + mf*16 + (lid&15); k-half = lid>>4
    uint32_t aob[2];
    #pragma unroll
    for (int mf = 0; mf < 2; mf++)
        aob[mf] = (uint32_t)((wm * 32 + mf * 16 + (lid & 15)) * 128 + ((lid >> 4) << 4));
    // B: row = wn*64 + jg*16 + (lid>>4)*8 + (lid&7); k-half = (lid>>3)&1
    uint32_t bob = (uint32_t)((wn * 64 + ((lid >> 4) << 3) + (lid & 7)) * 128
                              + (((lid >> 3) & 1) << 4));

    // Preload chunk 0
    load_chunk_async(Ahi, Alo, Bhi, Blo, bm, bn, 0, sb, tid);
    CP_COMMIT();
    CP_WAIT0();
    __syncthreads();

    for (int c = 0; c < NCHUNK; c++) {
        const uint32_t buf = sb + (c & 1) * BUF_B;
        if (c + 1 < NCHUNK) {
            load_chunk_async(Ahi, Alo, Bhi, Blo, bm, bn, (c + 1) * 128,
                             sb + ((c + 1) & 1) * BUF_B, tid);
            CP_COMMIT();
        }

        const uint32_t Ah_b = buf;
        const uint32_t Al_b = buf + TILE_B;
        const uint32_t Bh_b = buf + 2 * TILE_B;
        const uint32_t Bl_b = buf + 3 * TILE_B;

        #pragma unroll
        for (int ks = 0; ks < 4; ks++) {
            const uint32_t ko = (uint32_t)(ks * 32);
            uint32_t ah[2][4], al[2][4];
            #pragma unroll
            for (int mf = 0; mf < 2; mf++) {
                uint32_t ao = swz(aob[mf] + ko);
                LDSM_X4(ah[mf][0], ah[mf][1], ah[mf][2], ah[mf][3], Ah_b + ao);
                LDSM_X4(al[mf][0], al[mf][1], al[mf][2], al[mf][3], Al_b + ao);
            }
            #pragma unroll
            for (int jg = 0; jg < 4; jg++) {
                uint32_t bo = swz(bob + (uint32_t)(jg * 2048) + ko);
                uint32_t bh0, bh1, bh2, bh3, bl0, bl1, bl2, bl3;
                LDSM_X4(bh0, bh1, bh2, bh3, Bh_b + bo);
                LDSM_X4(bl0, bl1, bl2, bl3, Bl_b + bo);
                const int j0 = jg * 2, j1 = jg * 2 + 1;
                #pragma unroll
                for (int mf = 0; mf < 2; mf++) {
                    mma16816(acc[mf][j0], ah[mf], bh0, bh1);
                    mma16816(acc[mf][j1], ah[mf], bh2, bh3);
                    mma16816(acc[mf][j0], ah[mf], bl0, bl1);
                    mma16816(acc[mf][j1], ah[mf], bl2, bl3);
                    mma16816(acc[mf][j0], al[mf], bh0, bh1);
                    mma16816(acc[mf][j1], al[mf], bh2, bh3);
                }
            }
        }

        if (c + 1 < NCHUNK) {
            CP_WAIT0();
            __syncthreads();
        }
    }

    // Epilogue: registers -> global (float2 stores) + bias
    const int rbase = bm + wm * 32 + (lid >> 2);
    const int cbase = bn + wn * 64 + (lid & 3) * 2;
    #pragma unroll
    for (int j = 0; j < 8; j++) {
        const int col = cbase + j * 8;
        float2 bb = *(const float2*)&bias[col];
        #pragma unroll
        for (int mf = 0; mf < 2; mf++) {
            int r0 = rbase + mf * 16;
            float2 v0, v1;
            v0.x = acc[mf][j][0] + bb.x;
            v0.y = acc[mf][j][1] + bb.y;
            v1.x = acc[mf][j][2] + bb.x;
            v1.y = acc[mf][j][3] + bb.y;
            *(float2*)&C[(size_t)r0 * N + col]       = v0;
            *(float2*)&C[(size_t)(r0 + 8) * N + col] = v1;
        }
    }
}

// ---------------------------------------------------------------------------
// Flash attention (fp32, causal) — unchanged (Round-5 target)
// ---------------------------------------------------------------------------
__global__ __launch_bounds__(256) void attn_kernel(
    const float* __restrict__ qkv, float* __restrict__ att)
{
    __shared__ float Qs[64][64];
    __shared__ float KP[64][64];
    __shared__ float Vs[64][64];

    const int tid = threadIdx.x;
    const int tx  = tid & 15;
    const int ty  = tid >> 4;
    const int qt  = blockIdx.x;
    const int h   = blockIdx.y;
    const int b   = blockIdx.z;
    const int q0  = qt * 64;

    const size_t rstride = QKVCOLS;
    const float* qbase = qkv + (size_t)b * TSEQ * rstride + h * HDIM;
    const float* kbase = qbase + EMBED;
    const float* vbase = qbase + 2 * EMBED;

    const float scale = 0.125f;

    #pragma unroll
    for (int i = 0; i < 4; i++) {
        int f4 = tid + i * 256;
        int r  = f4 >> 4;
        int c4 = (f4 & 15) * 4;
        float4 v = *(const float4*)(qbase + (size_t)(q0 + r) * rstride + c4);
        Qs[c4 + 0][r] = v.x * scale;
        Qs[c4 + 1][r] = v.y * scale;
        Qs[c4 + 2][r] = v.z * scale;
        Qs[c4 + 3][r] = v.w * scale;
    }

    float m[4], l[4], o[4][4];
    #pragma unroll
    for (int i = 0; i < 4; i++) {
        m[i] = -1e30f; l[i] = 0.0f;
        #pragma unroll
        for (int j = 0; j < 4; j++) o[i][j] = 0.0f;
    }

    const int nk = qt + 1;
    for (int kt = 0; kt < nk; kt++) {
        const int k0 = kt * 64;
        __syncthreads();

        #pragma unroll
        for (int i = 0; i < 4; i++) {
            int f4 = tid + i * 256;
            int r  = f4 >> 4;
            int c4 = (f4 & 15) * 4;
            float4 kv = *(const float4*)(kbase + (size_t)(k0 + r) * rstride + c4);
            KP[c4 + 0][r] = kv.x;
            KP[c4 + 1][r] = kv.y;
            KP[c4 + 2][r] = kv.z;
            KP[c4 + 3][r] = kv.w;
            float4 vv = *(const float4*)(vbase + (size_t)(k0 + r) * rstride + c4);
            *(float4*)&Vs[r][c4] = vv;
        }
        __syncthreads();

        float s[4][4];
        #pragma unroll
        for (int i = 0; i < 4; i++)
            #pragma unroll
            for (int j = 0; j < 4; j++) s[i][j] = 0.0f;

        #pragma unroll 8
        for (int k = 0; k < 64; k++) {
            float4 aq = *(const float4*)&Qs[k][ty * 4];
            float4 bk = *(const float4*)&KP[k][tx * 4];
            float ar[4] = {aq.x, aq.y, aq.z, aq.w};
            float br[4] = {bk.x, bk.y, bk.z, bk.w};
            #pragma unroll
            for (int i = 0; i < 4; i++)
                #pragma unroll
                for (int j = 0; j < 4; j++)
                    s[i][j] = fmaf(ar[i], br[j], s[i][j]);
        }

        if (kt == qt) {
            #pragma unroll
            for (int i = 0; i < 4; i++) {
                int qg = q0 + ty * 4 + i;
                #pragma unroll
                for (int j = 0; j < 4; j++) {
                    int kg = k0 + tx * 4 + j;
                    if (kg > qg) s[i][j] = -1e30f;
                }
            }
        }

        #pragma unroll
        for (int i = 0; i < 4; i++) {
            float mx = s[i][0];
            mx = fmaxf(mx, s[i][1]);
            mx = fmaxf(mx, s[i][2]);
            mx = fmaxf(mx, s[i][3]);
            #pragma unroll
            for (int d = 1; d < 16; d <<= 1)
                mx = fmaxf(mx, __shfl_xor_sync(0xffffffffu, mx, d));
            float mnew = fmaxf(m[i], mx);
            float corr = __expf(m[i] - mnew);
            m[i] = mnew;
            float rs = 0.0f;
            #pragma unroll
            for (int j = 0; j < 4; j++) {
                float p = __expf(s[i][j] - mnew);
                s[i][j] = p;
                rs += p;
            }
            #pragma unroll
            for (int d = 1; d < 16; d <<= 1)
                rs += __shfl_xor_sync(0xffffffffu, rs, d);
            l[i] = l[i] * corr + rs;
            #pragma unroll
            for (int j = 0; j < 4; j++) o[i][j] *= corr;
        }

        __syncthreads();

        #pragma unroll
        for (int i = 0; i < 4; i++)
            #pragma unroll
            for (int j = 0; j < 4; j++)
                KP[ty * 4 + i][tx * 4 + j] = s[i][j];
        __syncthreads();

        #pragma unroll 8
        for (int c = 0; c < 64; c++) {
            float pv0 = KP[ty * 4 + 0][c];
            float pv1 = KP[ty * 4 + 1][c];
            float pv2 = KP[ty * 4 + 2][c];
            float pv3 = KP[ty * 4 + 3][c];
            float4 vv = *(const float4*)&Vs[c][tx * 4];
            o[0][0] = fmaf(pv0, vv.x, o[0][0]); o[0][1] = fmaf(pv0, vv.y, o[0][1]);
            o[0][2] = fmaf(pv0, vv.z, o[0][2]); o[0][3] = fmaf(pv0, vv.w, o[0][3]);
            o[1][0] = fmaf(pv1, vv.x, o[1][0]); o[1][1] = fmaf(pv1, vv.y, o[1][1]);
            o[1][2] = fmaf(pv1, vv.z, o[1][2]); o[1][3] = fmaf(pv1, vv.w, o[1][3]);
            o[2][0] = fmaf(pv2, vv.x, o[2][0]); o[2][1] = fmaf(pv2, vv.y, o[2][1]);
            o[2][2] = fmaf(pv2, vv.z, o[2][2]); o[2][3] = fmaf(pv2, vv.w, o[2][3]);
            o[3][0] = fmaf(pv3, vv.x, o[3][0]); o[3][1] = fmaf(pv3, vv.y, o[3][1]);
            o[3][2] = fmaf(pv3, vv.z, o[3][2]); o[3][3] = fmaf(pv3, vv.w, o[3][3]);
        }
    }

    #pragma unroll
    for (int i = 0; i < 4; i++) {
        float inv = 1.0f / l[i];
        int r = q0 + ty * 4 + i;
        float4 ov;
        ov.x = o[i][0] * inv;
        ov.y = o[i][1] * inv;
        ov.z = o[i][2] * inv;
        ov.w = o[i][3] * inv;
        *(float4*)&att[((size_t)(b * TSEQ + r)) * EMBED + h * HDIM + tx * 4] = ov;
    }
}

// ---------------------------------------------------------------------------
// Launch
// ---------------------------------------------------------------------------
extern "C" void kernel_launch(void* const* d_in, const int* in_sizes, int n_in,
                              void* d_out, int out_size)
{
    const float* x     = (const float*)d_in[0];
    const float* w_qkv = (const float*)d_in[1];
    const float* b_qkv = (const float*)d_in[2];
    const float* w_out = (const float*)d_in[3];
    const float* b_out = (const float*)d_in[4];
    float* out = (float*)d_out;

    float* qkv_ptr = nullptr;
    float* att_ptr = nullptr;
    __nv_bfloat16 *xa_hi, *xa_lo, *wq_hi, *wq_lo, *wo_hi, *wo_lo;
    cudaGetSymbolAddress((void**)&qkv_ptr, g_qkv);
    cudaGetSymbolAddress((void**)&att_ptr, g_att);
    cudaGetSymbolAddress((void**)&xa_hi, g_xa_hi);
    cudaGetSymbolAddress((void**)&xa_lo, g_xa_lo);
    cudaGetSymbolAddress((void**)&wq_hi, g_wq_hi);
    cudaGetSymbolAddress((void**)&wq_lo, g_wq_lo);
    cudaGetSymbolAddress((void**)&wo_hi, g_wo_hi);
    cudaGetSymbolAddress((void**)&wo_lo, g_wo_lo);

    cudaFuncSetAttribute(gemm_mma_kernel,
                         cudaFuncAttributeMaxDynamicSharedMemorySize, GEMM_SMEM);

    const int n4 = MTOK * EMBED / 4;

    // 1) split x, transpose+split weights
    split_kernel<<<(n4 + 255) / 256, 256>>>(x, xa_hi, xa_lo, n4);
    {
        dim3 g(QKVCOLS / 32, EMBED / 32);
        wsplit_kernel<<<g, dim3(32, 8)>>>(w_qkv, wq_hi, wq_lo, EMBED, QKVCOLS);
    }
    {
        dim3 g(EMBED / 32, EMBED / 32);
        wsplit_kernel<<<g, dim3(32, 8)>>>(w_out, wo_hi, wo_lo, EMBED, EMBED);
    }

    // 2) QKV projection on warp-mma tensor cores
    {
        dim3 grid(QKVCOLS / 128, MTOK / 128);
        gemm_mma_kernel<<<grid, 256, GEMM_SMEM>>>(xa_hi, xa_lo, wq_hi, wq_lo,
                                                  b_qkv, qkv_ptr, QKVCOLS);
    }

    // 3) Causal flash attention (fp32 SIMT — Round-5 target)
    {
        dim3 grid(TSEQ / 64, NHEAD, BATCH);
        attn_kernel<<<grid, 256>>>(qkv_ptr, att_ptr);
    }

    // 4) split attention output, out projection on warp-mma tensor cores
    split_kernel<<<(n4 + 255) / 256, 256>>>(att_ptr, xa_hi, xa_lo, n4);
    {
        dim3 grid(EMBED / 128, MTOK / 128);
        gemm_mma_kernel<<<grid, 256, GEMM_SMEM>>>(xa_hi, xa_lo, wo_hi, wo_lo,
                                                  b_out, out, EMBED);
    }
}

// round 8
// speedup vs baseline: 3.3184x; 3.3184x over previous
#include <cuda_runtime.h>
#include <cuda_bf16.h>
#include <cstdint>
#include <math.h>

// Problem constants
#define BATCH   2
#define TSEQ    2048
#define EMBED   1024
#define NHEAD   16
#define HDIM    64
#define MTOK    (BATCH * TSEQ)        // 4096
#define QKVCOLS (3 * EMBED)           // 3072

// Scratch (allocation-free rule: __device__ globals)
__device__ float         g_qkv[(size_t)MTOK * QKVCOLS];    // [4096, 3072]
__device__ __nv_bfloat16 g_xa_hi[(size_t)MTOK * EMBED];    // x split / attn out split
__device__ __nv_bfloat16 g_xa_lo[(size_t)MTOK * EMBED];
__device__ __nv_bfloat16 g_wq_hi[(size_t)QKVCOLS * EMBED]; // w_qkv^T [3072][1024]
__device__ __nv_bfloat16 g_wq_lo[(size_t)QKVCOLS * EMBED];
__device__ __nv_bfloat16 g_wo_hi[(size_t)EMBED * EMBED];   // w_out^T [1024][1024]
__device__ __nv_bfloat16 g_wo_lo[(size_t)EMBED * EMBED];
// per-head split qkv: [b][h][t][64]
__device__ __nv_bfloat16 g_qh[(size_t)MTOK * EMBED];
__device__ __nv_bfloat16 g_ql[(size_t)MTOK * EMBED];
__device__ __nv_bfloat16 g_kh[(size_t)MTOK * EMBED];
__device__ __nv_bfloat16 g_kl[(size_t)MTOK * EMBED];
__device__ __nv_bfloat16 g_vh[(size_t)MTOK * EMBED];
__device__ __nv_bfloat16 g_vl[(size_t)MTOK * EMBED];

// ---------------------------------------------------------------------------
// PTX helpers (plain sm_80+ PTX)
// ---------------------------------------------------------------------------
__device__ __forceinline__ uint32_t smem_u32(const void* p) {
    uint32_t a;
    asm("{ .reg .u64 t; cvta.to.shared.u64 t, %1; cvt.u32.u64 %0, t; }"
        : "=r"(a) : "l"(p));
    return a;
}

#define CP_ASYNC16(dst, src) \
    asm volatile("cp.async.cg.shared.global [%0], [%1], 16;" :: "r"(dst), "l"(src))
#define CP_COMMIT()  asm volatile("cp.async.commit_group;" ::: "memory")
#define CP_WAIT0()   asm volatile("cp.async.wait_group 0;" ::: "memory")

#define LDSM_X4(r0, r1, r2, r3, a) \
    asm volatile("ldmatrix.sync.aligned.m8n8.x4.shared.b16 {%0,%1,%2,%3}, [%4];" \
                 : "=r"(r0), "=r"(r1), "=r"(r2), "=r"(r3) : "r"(a))
#define LDSM_X4_T(r0, r1, r2, r3, a) \
    asm volatile("ldmatrix.sync.aligned.m8n8.x4.trans.shared.b16 {%0,%1,%2,%3}, [%4];" \
                 : "=r"(r0), "=r"(r1), "=r"(r2), "=r"(r3) : "r"(a))

__device__ __forceinline__ void mma16816(float* d, const uint32_t* a,
                                         uint32_t b0, uint32_t b1) {
    asm volatile(
        "mma.sync.aligned.m16n8k16.row.col.f32.bf16.bf16.f32 "
        "{%0,%1,%2,%3}, {%4,%5,%6,%7}, {%8,%9}, {%0,%1,%2,%3};"
        : "+f"(d[0]), "+f"(d[1]), "+f"(d[2]), "+f"(d[3])
        : "r"(a[0]), "r"(a[1]), "r"(a[2]), "r"(a[3]), "r"(b0), "r"(b1));
}

__device__ __forceinline__ uint32_t swz(uint32_t o) {
    return o ^ ((o >> 3) & 0x70);
}

// Split pair of floats into packed bf16 hi + bf16 lo residual
__device__ __forceinline__ void split2(float a, float b, uint32_t& h, uint32_t& l) {
    __nv_bfloat16 ha = __float2bfloat16(a), hb = __float2bfloat16(b);
    float ra = a - __bfloat162float(ha);
    float rb = b - __bfloat162float(hb);
    __nv_bfloat162 H(ha, hb);
    __nv_bfloat162 L(__float2bfloat16(ra), __float2bfloat16(rb));
    h = *(uint32_t*)&H;
    l = *(uint32_t*)&L;
}

// ---------------------------------------------------------------------------
// Prep: split fp32 -> bf16 hi/lo (elementwise)
// ---------------------------------------------------------------------------
__global__ __launch_bounds__(256) void split_kernel(
    const float* __restrict__ src, __nv_bfloat16* __restrict__ hi,
    __nv_bfloat16* __restrict__ lo, int n4)
{
    int i = blockIdx.x * blockDim.x + threadIdx.x;
    if (i >= n4) return;
    float4 v = ((const float4*)src)[i];
    uint32_t h0, l0, h1, l1;
    split2(v.x, v.y, h0, l0);
    split2(v.z, v.w, h1, l1);
    uint32_t* hp = (uint32_t*)hi;
    uint32_t* lp = (uint32_t*)lo;
    hp[2*i] = h0; hp[2*i+1] = h1;
    lp[2*i] = l0; lp[2*i+1] = l1;
}

// ---------------------------------------------------------------------------
// Prep: transpose + split weights. W[K][N] fp32 -> WT_hi/lo [N][K] bf16
// ---------------------------------------------------------------------------
__global__ __launch_bounds__(256) void wsplit_kernel(
    const float* __restrict__ W, __nv_bfloat16* __restrict__ Thi,
    __nv_bfloat16* __restrict__ Tlo, int K, int N)
{
    __shared__ float t[32][33];
    int tx = threadIdx.x, ty = threadIdx.y;       // 32 x 8
    int k0 = blockIdx.y * 32, n0 = blockIdx.x * 32;
    #pragma unroll
    for (int i = 0; i < 4; i++)
        t[ty + i * 8][tx] = W[(size_t)(k0 + ty + i * 8) * N + n0 + tx];
    __syncthreads();
    #pragma unroll
    for (int i = 0; i < 4; i++) {
        float v = t[tx][ty + i * 8];
        __nv_bfloat16 h = __float2bfloat16(v);
        __nv_bfloat16 l = __float2bfloat16(v - __bfloat162float(h));
        size_t o = (size_t)(n0 + ty + i * 8) * K + k0 + tx;
        Thi[o] = h;
        Tlo[o] = l;
    }
}

// ---------------------------------------------------------------------------
// Prep: split qkv fp32 [4096][3072] into per-head bf16 hi/lo [b][h][t][64].
// Q is pre-scaled by 1/sqrt(64) before splitting.
// ---------------------------------------------------------------------------
__global__ __launch_bounds__(256) void qkv_split_kernel(
    const float* __restrict__ qkv,
    __nv_bfloat16* __restrict__ qh, __nv_bfloat16* __restrict__ ql,
    __nv_bfloat16* __restrict__ kh, __nv_bfloat16* __restrict__ kl,
    __nv_bfloat16* __restrict__ vh, __nv_bfloat16* __restrict__ vl)
{
    int i = blockIdx.x * blockDim.x + threadIdx.x;
    if (i >= MTOK * QKVCOLS / 4) return;
    int flat = i * 4;
    int tg = flat / QKVCOLS;             // 0..4095
    int c  = flat - tg * QKVCOLS;
    int sec = c >> 10, r = c & 1023, h = r >> 6, d = r & 63;
    float4 v = *(const float4*)(qkv + (size_t)tg * QKVCOLS + c);
    if (sec == 0) { v.x *= 0.125f; v.y *= 0.125f; v.z *= 0.125f; v.w *= 0.125f; }
    uint32_t h0, l0, h1, l1;
    split2(v.x, v.y, h0, l0);
    split2(v.z, v.w, h1, l1);
    int b = tg >> 11, t = tg & 2047;
    size_t off = (((size_t)(b * NHEAD + h)) * TSEQ + t) * HDIM + d;
    __nv_bfloat16 *H, *L;
    if (sec == 0)      { H = qh; L = ql; }
    else if (sec == 1) { H = kh; L = kl; }
    else               { H = vh; L = vl; }
    uint32_t* Hp = (uint32_t*)(H + off);
    uint32_t* Lp = (uint32_t*)(L + off);
    Hp[0] = h0; Hp[1] = h1;
    Lp[0] = l0; Lp[1] = l1;
}

// ---------------------------------------------------------------------------
// Warp-mma GEMM (unchanged from R7): C = Ahi/lo @ (Bhi/lo)^T + bias
// ---------------------------------------------------------------------------
#define GK      1024
#define NCHUNK  16
#define TILE_B  16384
#define BUF_B   (4 * TILE_B)
#define GEMM_SMEM (2 * BUF_B)

__device__ __forceinline__ void load_chunk_async(
    const __nv_bfloat16* __restrict__ Ahi, const __nv_bfloat16* __restrict__ Alo,
    const __nv_bfloat16* __restrict__ Bhi, const __nv_bfloat16* __restrict__ Blo,
    int bm, int bn, int kbyte, uint32_t buf, int tid)
{
    #pragma unroll
    for (int i = 0; i < 4; i++) {
        int idx = tid + i * 256;
        int r   = idx >> 3;
        int cb  = (idx & 7) * 16;
        uint32_t so = swz((uint32_t)(r * 128 + cb));
        const char* gA = (const char*)(Ahi + (size_t)(bm + r) * GK) + kbyte + cb;
        const char* gAl= (const char*)(Alo + (size_t)(bm + r) * GK) + kbyte + cb;
        const char* gB = (const char*)(Bhi + (size_t)(bn + r) * GK) + kbyte + cb;
        const char* gBl= (const char*)(Blo + (size_t)(bn + r) * GK) + kbyte + cb;
        CP_ASYNC16(buf + so,              gA);
        CP_ASYNC16(buf + TILE_B + so,     gAl);
        CP_ASYNC16(buf + 2 * TILE_B + so, gB);
        CP_ASYNC16(buf + 3 * TILE_B + so, gBl);
    }
}

__global__ __launch_bounds__(256) void gemm_mma_kernel(
    const __nv_bfloat16* __restrict__ Ahi, const __nv_bfloat16* __restrict__ Alo,
    const __nv_bfloat16* __restrict__ Bhi, const __nv_bfloat16* __restrict__ Blo,
    const float* __restrict__ bias, float* __restrict__ C, int N)
{
    extern __shared__ char smem[];
    const uint32_t sb = smem_u32(smem);
    const int tid = threadIdx.x;
    const int wid = tid >> 5;
    const int lid = tid & 31;
    const int wm  = wid >> 1;
    const int wn  = wid & 1;

    const int bm = blockIdx.y * 128;
    const int bn = blockIdx.x * 128;

    float acc[2][8][4];
    #pragma unroll
    for (int a = 0; a < 2; a++)
        #pragma unroll
        for (int j = 0; j < 8; j++)
            #pragma unroll
            for (int k = 0; k < 4; k++) acc[a][j][k] = 0.0f;

    uint32_t aob[2];
    #pragma unroll
    for (int mf = 0; mf < 2; mf++)
        aob[mf] = (uint32_t)((wm * 32 + mf * 16 + (lid & 15)) * 128 + ((lid >> 4) << 4));
    uint32_t bob = (uint32_t)((wn * 64 + ((lid >> 4) << 3) + (lid & 7)) * 128
                              + (((lid >> 3) & 1) << 4));

    load_chunk_async(Ahi, Alo, Bhi, Blo, bm, bn, 0, sb, tid);
    CP_COMMIT();
    CP_WAIT0();
    __syncthreads();

    for (int c = 0; c < NCHUNK; c++) {
        const uint32_t buf = sb + (c & 1) * BUF_B;
        if (c + 1 < NCHUNK) {
            load_chunk_async(Ahi, Alo, Bhi, Blo, bm, bn, (c + 1) * 128,
                             sb + ((c + 1) & 1) * BUF_B, tid);
            CP_COMMIT();
        }

        const uint32_t Ah_b = buf;
        const uint32_t Al_b = buf + TILE_B;
        const uint32_t Bh_b = buf + 2 * TILE_B;
        const uint32_t Bl_b = buf + 3 * TILE_B;

        #pragma unroll
        for (int ks = 0; ks < 4; ks++) {
            const uint32_t ko = (uint32_t)(ks * 32);
            uint32_t ah[2][4], al[2][4];
            #pragma unroll
            for (int mf = 0; mf < 2; mf++) {
                uint32_t ao = swz(aob[mf] + ko);
                LDSM_X4(ah[mf][0], ah[mf][1], ah[mf][2], ah[mf][3], Ah_b + ao);
                LDSM_X4(al[mf][0], al[mf][1], al[mf][2], al[mf][3], Al_b + ao);
            }
            #pragma unroll
            for (int jg = 0; jg < 4; jg++) {
                uint32_t bo = swz(bob + (uint32_t)(jg * 2048) + ko);
                uint32_t bh0, bh1, bh2, bh3, bl0, bl1, bl2, bl3;
                LDSM_X4(bh0, bh1, bh2, bh3, Bh_b + bo);
                LDSM_X4(bl0, bl1, bl2, bl3, Bl_b + bo);
                const int j0 = jg * 2, j1 = jg * 2 + 1;
                #pragma unroll
                for (int mf = 0; mf < 2; mf++) {
                    mma16816(acc[mf][j0], ah[mf], bh0, bh1);
                    mma16816(acc[mf][j1], ah[mf], bh2, bh3);
                    mma16816(acc[mf][j0], ah[mf], bl0, bl1);
                    mma16816(acc[mf][j1], ah[mf], bl2, bl3);
                    mma16816(acc[mf][j0], al[mf], bh0, bh1);
                    mma16816(acc[mf][j1], al[mf], bh2, bh3);
                }
            }
        }

        if (c + 1 < NCHUNK) {
            CP_WAIT0();
            __syncthreads();
        }
    }

    const int rbase = bm + wm * 32 + (lid >> 2);
    const int cbase = bn + wn * 64 + (lid & 3) * 2;
    #pragma unroll
    for (int j = 0; j < 8; j++) {
        const int col = cbase + j * 8;
        float2 bb = *(const float2*)&bias[col];
        #pragma unroll
        for (int mf = 0; mf < 2; mf++) {
            int r0 = rbase + mf * 16;
            float2 v0, v1;
            v0.x = acc[mf][j][0] + bb.x;
            v0.y = acc[mf][j][1] + bb.y;
            v1.x = acc[mf][j][2] + bb.x;
            v1.y = acc[mf][j][3] + bb.y;
            *(float2*)&C[(size_t)r0 * N + col]       = v0;
            *(float2*)&C[(size_t)(r0 + 8) * N + col] = v1;
        }
    }
}

// ---------------------------------------------------------------------------
// Tensor-core flash attention (split-bf16, causal).
// CTA: 128 Q rows x (head, batch). 8 warps; warp w owns rows [w*16, w*16+16).
// KV tiles of 64 keys, double-buffered. Output written as bf16 hi/lo splits
// directly into the out-projection's A buffers.
// smem: Qh/Ql 2x16KB + 2 KV buffers x (Kh,Kl,Vh,Vl = 32KB) = 96KB.
// ---------------------------------------------------------------------------
#define AT_QH    0
#define AT_QL    16384
#define AT_KV    32768
#define AT_KVB   32768          // per-buffer bytes
#define AT_SMEM  (AT_KV + 2 * AT_KVB)   // 98304

__device__ __forceinline__ void attn_load_kv(
    const char* kh, const char* kl, const char* vh, const char* vl,
    uint32_t buf, int tid)
{
    #pragma unroll
    for (int i = 0; i < 2; i++) {
        int idx = tid + i * 256;          // 0..511
        int r   = idx >> 3;               // 0..63
        int cb  = (idx & 7) * 16;
        uint32_t so = swz((uint32_t)(r * 128 + cb));
        int go = r * 128 + cb;
        CP_ASYNC16(buf + so,          kh + go);
        CP_ASYNC16(buf + 8192 + so,   kl + go);
        CP_ASYNC16(buf + 16384 + so,  vh + go);
        CP_ASYNC16(buf + 24576 + so,  vl + go);
    }
}

__global__ __launch_bounds__(256) void attn_mma_kernel(
    const __nv_bfloat16* __restrict__ Qh, const __nv_bfloat16* __restrict__ Ql,
    const __nv_bfloat16* __restrict__ Kh, const __nv_bfloat16* __restrict__ Kl,
    const __nv_bfloat16* __restrict__ Vh, const __nv_bfloat16* __restrict__ Vl,
    __nv_bfloat16* __restrict__ Ohi, __nv_bfloat16* __restrict__ Olo)
{
    extern __shared__ char smem[];
    const uint32_t sb = smem_u32(smem);
    const int tid = threadIdx.x;
    const int w   = tid >> 5;
    const int lid = tid & 31;
    const int q0  = blockIdx.x * 128;
    const int h   = blockIdx.y;
    const int b   = blockIdx.z;

    const size_t headbase = ((size_t)(b * NHEAD + h)) * TSEQ * HDIM;  // elements
    const char* qh_g = (const char*)(Qh + headbase + (size_t)q0 * HDIM);
    const char* ql_g = (const char*)(Ql + headbase + (size_t)q0 * HDIM);
    const char* kh_g = (const char*)(Kh + headbase);
    const char* kl_g = (const char*)(Kl + headbase);
    const char* vh_g = (const char*)(Vh + headbase);
    const char* vl_g = (const char*)(Vl + headbase);

    // Preload Q (hi+lo, 16KB each) and KV tile 0
    #pragma unroll
    for (int i = 0; i < 4; i++) {
        int idx = tid + i * 256;          // 0..1023
        int r   = idx >> 3;               // 0..127
        int cb  = (idx & 7) * 16;
        uint32_t so = swz((uint32_t)(r * 128 + cb));
        int go = r * 128 + cb;
        CP_ASYNC16(sb + AT_QH + so, qh_g + go);
        CP_ASYNC16(sb + AT_QL + so, ql_g + go);
    }
    attn_load_kv(kh_g, kl_g, vh_g, vl_g, sb + AT_KV, tid);
    CP_COMMIT();
    CP_WAIT0();
    __syncthreads();

    // Q fragments (held in registers for the whole CTA lifetime)
    uint32_t aqh[4][4], aql[4][4];
    {
        uint32_t abase = (uint32_t)((w * 16 + (lid & 15)) * 128 + ((lid >> 4) << 4));
        #pragma unroll
        for (int ks = 0; ks < 4; ks++) {
            uint32_t ao = swz(abase + ks * 32);
            LDSM_X4(aqh[ks][0], aqh[ks][1], aqh[ks][2], aqh[ks][3], sb + AT_QH + ao);
            LDSM_X4(aql[ks][0], aql[ks][1], aql[ks][2], aql[ks][3], sb + AT_QL + ao);
        }
    }

    float o[8][4];
    #pragma unroll
    for (int j = 0; j < 8; j++)
        #pragma unroll
        for (int e = 0; e < 4; e++) o[j][e] = 0.0f;
    float m0 = -1e30f, m1 = -1e30f, l0 = 0.0f, l1 = 0.0f;

    const int row0 = q0 + w * 16 + (lid >> 2);
    const int row1 = row0 + 8;
    const uint32_t kbob = (uint32_t)((((lid >> 4) << 3) + (lid & 7)) * 128
                                     + (((lid >> 3) & 1) << 4));
    const uint32_t vbob = (uint32_t)(((lid & 7) + (((lid >> 3) & 1) << 3)) * 128
                                     + ((lid >> 4) << 4));

    const int nk = 2 * blockIdx.x + 2;
    for (int kt = 0; kt < nk; kt++) {
        const uint32_t buf = sb + AT_KV + (kt & 1) * AT_KVB;
        if (kt + 1 < nk) {
            int ko = (kt + 1) * 64 * 128;   // byte offset of next tile
            attn_load_kv(kh_g + ko, kl_g + ko, vh_g + ko, vl_g + ko,
                         sb + AT_KV + ((kt + 1) & 1) * AT_KVB, tid);
            CP_COMMIT();
        }

        // ---- S = Q @ K^T (3-term split) ----
        float s[8][4];
        #pragma unroll
        for (int j = 0; j < 8; j++)
            #pragma unroll
            for (int e = 0; e < 4; e++) s[j][e] = 0.0f;

        const uint32_t Kh_b = buf, Kl_b = buf + 8192;
        #pragma unroll
        for (int ks = 0; ks < 4; ks++) {
            #pragma unroll
            for (int jg = 0; jg < 4; jg++) {
                uint32_t bo = swz(kbob + (uint32_t)(jg * 2048 + ks * 32));
                uint32_t kh0, kh1, kh2, kh3, kl0c, kl1c, kl2c, kl3c;
                LDSM_X4(kh0, kh1, kh2, kh3, Kh_b + bo);
                LDSM_X4(kl0c, kl1c, kl2c, kl3c, Kl_b + bo);
                const int j0 = jg * 2, j1 = jg * 2 + 1;
                mma16816(s[j0], aqh[ks], kh0, kh1);
                mma16816(s[j1], aqh[ks], kh2, kh3);
                mma16816(s[j0], aqh[ks], kl0c, kl1c);
                mma16816(s[j1], aqh[ks], kl2c, kl3c);
                mma16816(s[j0], aql[ks], kh0, kh1);
                mma16816(s[j1], aql[ks], kh2, kh3);
            }
        }

        // ---- causal mask (boundary tiles only) ----
        if (kt * 64 + 63 > q0 + w * 16) {
            const int kc0 = kt * 64 + 2 * (lid & 3);
            #pragma unroll
            for (int j = 0; j < 8; j++) {
                int col = kc0 + 8 * j;
                if (col     > row0) s[j][0] = -1e30f;
                if (col + 1 > row0) s[j][1] = -1e30f;
                if (col     > row1) s[j][2] = -1e30f;
                if (col + 1 > row1) s[j][3] = -1e30f;
            }
        }

        // ---- online softmax ----
        float mx0 = -1e30f, mx1 = -1e30f;
        #pragma unroll
        for (int j = 0; j < 8; j++) {
            mx0 = fmaxf(mx0, fmaxf(s[j][0], s[j][1]));
            mx1 = fmaxf(mx1, fmaxf(s[j][2], s[j][3]));
        }
        mx0 = fmaxf(mx0, __shfl_xor_sync(0xffffffffu, mx0, 1));
        mx0 = fmaxf(mx0, __shfl_xor_sync(0xffffffffu, mx0, 2));
        mx1 = fmaxf(mx1, __shfl_xor_sync(0xffffffffu, mx1, 1));
        mx1 = fmaxf(mx1, __shfl_xor_sync(0xffffffffu, mx1, 2));
        float mn0 = fmaxf(m0, mx0), mn1 = fmaxf(m1, mx1);
        float corr0 = __expf(m0 - mn0), corr1 = __expf(m1 - mn1);
        m0 = mn0; m1 = mn1;
        float rs0 = 0.0f, rs1 = 0.0f;
        #pragma unroll
        for (int j = 0; j < 8; j++) {
            s[j][0] = __expf(s[j][0] - mn0);
            s[j][1] = __expf(s[j][1] - mn0);
            s[j][2] = __expf(s[j][2] - mn1);
            s[j][3] = __expf(s[j][3] - mn1);
            rs0 += s[j][0] + s[j][1];
            rs1 += s[j][2] + s[j][3];
        }
        rs0 += __shfl_xor_sync(0xffffffffu, rs0, 1);
        rs0 += __shfl_xor_sync(0xffffffffu, rs0, 2);
        rs1 += __shfl_xor_sync(0xffffffffu, rs1, 1);
        rs1 += __shfl_xor_sync(0xffffffffu, rs1, 2);
        l0 = l0 * corr0 + rs0;
        l1 = l1 * corr1 + rs1;
        #pragma unroll
        for (int j = 0; j < 8; j++) {
            o[j][0] *= corr0; o[j][1] *= corr0;
            o[j][2] *= corr1; o[j][3] *= corr1;
        }

        // ---- pack P into split bf16 A-fragments ----
        uint32_t ph[4][4], pl[4][4];
        #pragma unroll
        for (int ks = 0; ks < 4; ks++) {
            const int t0 = 2 * ks, t1 = 2 * ks + 1;
            split2(s[t0][0], s[t0][1], ph[ks][0], pl[ks][0]);
            split2(s[t0][2], s[t0][3], ph[ks][1], pl[ks][1]);
            split2(s[t1][0], s[t1][1], ph[ks][2], pl[ks][2]);
            split2(s[t1][2], s[t1][3], ph[ks][3], pl[ks][3]);
        }

        // ---- O += P @ V (3-term split) ----
        const uint32_t Vh_b = buf + 16384, Vl_b = buf + 24576;
        #pragma unroll
        for (int ks = 0; ks < 4; ks++) {
            #pragma unroll
            for (int dg = 0; dg < 4; dg++) {
                uint32_t vo = swz(vbob + (uint32_t)(ks * 16 * 128 + dg * 32));
                uint32_t vh0, vh1, vh2, vh3, vl0c, vl1c, vl2c, vl3c;
                LDSM_X4_T(vh0, vh1, vh2, vh3, Vh_b + vo);
                LDSM_X4_T(vl0c, vl1c, vl2c, vl3c, Vl_b + vo);
                const int d0 = dg * 2, d1 = dg * 2 + 1;
                mma16816(o[d0], ph[ks], vh0, vh1);
                mma16816(o[d1], ph[ks], vh2, vh3);
                mma16816(o[d0], ph[ks], vl0c, vl1c);
                mma16816(o[d1], ph[ks], vl2c, vl3c);
                mma16816(o[d0], pl[ks], vh0, vh1);
                mma16816(o[d1], pl[ks], vh2, vh3);
            }
        }

        if (kt + 1 < nk) {
            CP_WAIT0();
            __syncthreads();
        }
    }

    // ---- epilogue: normalize, split to bf16 hi/lo, write [t][h*64+d] ----
    const float inv0 = 1.0f / l0;
    const float inv1 = 1.0f / l1;
    const size_t ro0 = ((size_t)(b * TSEQ) + row0) * EMBED + h * HDIM;
    const size_t ro1 = ((size_t)(b * TSEQ) + row1) * EMBED + h * HDIM;
    #pragma unroll
    for (int j = 0; j < 8; j++) {
        const int col = 8 * j + 2 * (lid & 3);
        uint32_t H, L;
        split2(o[j][0] * inv0, o[j][1] * inv0, H, L);
        *(uint32_t*)(Ohi + ro0 + col) = H;
        *(uint32_t*)(Olo + ro0 + col) = L;
        split2(o[j][2] * inv1, o[j][3] * inv1, H, L);
        *(uint32_t*)(Ohi + ro1 + col) = H;
        *(uint32_t*)(Olo + ro1 + col) = L;
    }
}

// ---------------------------------------------------------------------------
// Launch
// ---------------------------------------------------------------------------
extern "C" void kernel_launch(void* const* d_in, const int* in_sizes, int n_in,
                              void* d_out, int out_size)
{
    const float* x     = (const float*)d_in[0];
    const float* w_qkv = (const float*)d_in[1];
    const float* b_qkv = (const float*)d_in[2];
    const float* w_out = (const float*)d_in[3];
    const float* b_out = (const float*)d_in[4];
    float* out = (float*)d_out;

    float* qkv_ptr = nullptr;
    __nv_bfloat16 *xa_hi, *xa_lo, *wq_hi, *wq_lo, *wo_hi, *wo_lo;
    __nv_bfloat16 *qh, *ql, *kh, *kl, *vh, *vl;
    cudaGetSymbolAddress((void**)&qkv_ptr, g_qkv);
    cudaGetSymbolAddress((void**)&xa_hi, g_xa_hi);
    cudaGetSymbolAddress((void**)&xa_lo, g_xa_lo);
    cudaGetSymbolAddress((void**)&wq_hi, g_wq_hi);
    cudaGetSymbolAddress((void**)&wq_lo, g_wq_lo);
    cudaGetSymbolAddress((void**)&wo_hi, g_wo_hi);
    cudaGetSymbolAddress((void**)&wo_lo, g_wo_lo);
    cudaGetSymbolAddress((void**)&qh, g_qh);
    cudaGetSymbolAddress((void**)&ql, g_ql);
    cudaGetSymbolAddress((void**)&kh, g_kh);
    cudaGetSymbolAddress((void**)&kl, g_kl);
    cudaGetSymbolAddress((void**)&vh, g_vh);
    cudaGetSymbolAddress((void**)&vl, g_vl);

    cudaFuncSetAttribute(gemm_mma_kernel,
                         cudaFuncAttributeMaxDynamicSharedMemorySize, GEMM_SMEM);
    cudaFuncSetAttribute(attn_mma_kernel,
                         cudaFuncAttributeMaxDynamicSharedMemorySize, AT_SMEM);

    const int n4 = MTOK * EMBED / 4;

    // 1) split x, transpose+split weights
    split_kernel<<<(n4 + 255) / 256, 256>>>(x, xa_hi, xa_lo, n4);
    {
        dim3 g(QKVCOLS / 32, EMBED / 32);
        wsplit_kernel<<<g, dim3(32, 8)>>>(w_qkv, wq_hi, wq_lo, EMBED, QKVCOLS);
    }
    {
        dim3 g(EMBED / 32, EMBED / 32);
        wsplit_kernel<<<g, dim3(32, 8)>>>(w_out, wo_hi, wo_lo, EMBED, EMBED);
    }

    // 2) QKV projection (tensor cores)
    {
        dim3 grid(QKVCOLS / 128, MTOK / 128);
        gemm_mma_kernel<<<grid, 256, GEMM_SMEM>>>(xa_hi, xa_lo, wq_hi, wq_lo,
                                                  b_qkv, qkv_ptr, QKVCOLS);
    }

    // 3) split qkv into per-head bf16 hi/lo (q pre-scaled)
    {
        int nt = MTOK * QKVCOLS / 4;
        qkv_split_kernel<<<(nt + 255) / 256, 256>>>(qkv_ptr, qh, ql, kh, kl, vh, vl);
    }

    // 4) tensor-core flash attention -> writes split output into xa_hi/lo
    {
        dim3 grid(TSEQ / 128, NHEAD, BATCH);
        attn_mma_kernel<<<grid, 256, AT_SMEM>>>(qh, ql, kh, kl, vh, vl,
                                                xa_hi, xa_lo);
    }

    // 5) output projection (tensor cores)
    {
        dim3 grid(EMBED / 128, MTOK / 128);
        gemm_mma_kernel<<<grid, 256, GEMM_SMEM>>>(xa_hi, xa_lo, wo_hi, wo_lo,
                                                  b_out, out, EMBED);
    }
}